// round 1
// baseline (speedup 1.0000x reference)
#include <cuda_runtime.h>
#include <cuda_bf16.h>
#include <cstdint>

#define BATCH 4096
#define DIM   1024
#define NC    1000
#define NTOT  5096          // BATCH + NC
#define NPAD  5120          // padded to multiple of 128
#define TAU_INV 10.0f
#define EPSF 1e-8f

#define BM 128
#define BN 128
#define BK 32
#define LDA 40              // BK + 8 halves pad (row stride 80B, 16B aligned, ldmatrix conflict-free)
#define NBLK (NPAD / BN)    // 40 column blocks

// ---- scratch (no allocations allowed) ----
__device__ __nv_bfloat16 g_Fb[BATCH * DIM];        // features bf16
__device__ __nv_bfloat16 g_Gb[NPAD * DIM];         // [features; centers; zero-pad] bf16
__device__ float g_w[NPAD];                        // per-column denom weight
__device__ int   g_cls[NPAD];                      // per-column class (-1 for pad)
__device__ int   g_counts[NC];
__device__ float g_dpart[NBLK * BATCH];            // [colblock][row] partial denom
__device__ float g_ppart[NBLK * BATCH];            // [colblock][row] partial pos-log-sum

// ---------------- prep kernels ----------------
__global__ void k_zero_counts() {
    if (threadIdx.x < NC) g_counts[threadIdx.x] = 0;
}

__global__ void k_count(const int* __restrict__ targets) {
    int i = blockIdx.x * blockDim.x + threadIdx.x;
    if (i < BATCH) atomicAdd(&g_counts[targets[i]], 1);
}

__global__ void k_wcls(const int* __restrict__ targets) {
    int k = blockIdx.x * blockDim.x + threadIdx.x;
    if (k >= NPAD) return;
    if (k < BATCH) {
        int t = targets[k];
        g_w[k]   = 1.0f / (float)(g_counts[t] + 1);
        g_cls[k] = t;
    } else if (k < NTOT) {
        int j = k - BATCH;
        g_w[k]   = 1.0f / (float)(g_counts[j] + 1);
        g_cls[k] = j;
    } else {
        g_w[k]   = 0.0f;
        g_cls[k] = -1;
    }
}

__global__ void k_convert(const float* __restrict__ features,
                          const float* __restrict__ centers) {
    int idx = blockIdx.x * blockDim.x + threadIdx.x;
    if (idx >= NPAD * DIM) return;
    int row = idx >> 10;  // DIM = 1024
    float v;
    if (row < BATCH) {
        v = features[idx];
        g_Fb[idx] = __float2bfloat16_rn(v);
    } else if (row < NTOT) {
        v = centers[idx - BATCH * DIM];
    } else {
        v = 0.0f;
    }
    g_Gb[idx] = __float2bfloat16_rn(v);
}

// ---------------- mma helpers ----------------
__device__ __forceinline__ void ldmatrix_x4(uint32_t& r0, uint32_t& r1, uint32_t& r2, uint32_t& r3,
                                            uint32_t addr) {
    asm volatile("ldmatrix.sync.aligned.m8n8.x4.shared.b16 {%0,%1,%2,%3}, [%4];"
                 : "=r"(r0), "=r"(r1), "=r"(r2), "=r"(r3) : "r"(addr));
}
__device__ __forceinline__ void ldmatrix_x2(uint32_t& r0, uint32_t& r1, uint32_t addr) {
    asm volatile("ldmatrix.sync.aligned.m8n8.x2.shared.b16 {%0,%1}, [%2];"
                 : "=r"(r0), "=r"(r1) : "r"(addr));
}
__device__ __forceinline__ void mma16816(float* c, uint32_t a0, uint32_t a1, uint32_t a2, uint32_t a3,
                                         uint32_t b0, uint32_t b1) {
    asm volatile(
        "mma.sync.aligned.m16n8k16.row.col.f32.bf16.bf16.f32 "
        "{%0,%1,%2,%3}, {%4,%5,%6,%7}, {%8,%9}, {%0,%1,%2,%3};"
        : "+f"(c[0]), "+f"(c[1]), "+f"(c[2]), "+f"(c[3])
        : "r"(a0), "r"(a1), "r"(a2), "r"(a3), "r"(b0), "r"(b1));
}

// ---------------- fused GEMM + epilogue ----------------
// S = (F Gt) * TAU_INV tilewise; epilogue reduces exp(S)*w into denom partials
// and predicated log(exp(S)+eps) into pos partials, per row, per column-block.
__global__ __launch_bounds__(256) void k_gemm() {
    __shared__ __align__(16) __nv_bfloat16 sA[2][BM * LDA];
    __shared__ __align__(16) __nv_bfloat16 sB[2][BN * LDA];
    __shared__ float red_d[BM];
    __shared__ float red_p[BM];

    const int tid  = threadIdx.x;
    const int warp = tid >> 5;
    const int lane = tid & 31;
    const int wm = warp >> 2;       // 0..1  (64-row slab)
    const int wn = warp & 3;        // 0..3  (32-col slab)
    const int bm = blockIdx.y, bn = blockIdx.x;
    const int rowBase = bm * BM;
    const int colBase = bn * BN;

    if (tid < BM) { red_d[tid] = 0.0f; red_p[tid] = 0.0f; }

    float acc[4][4][4];
#pragma unroll
    for (int a = 0; a < 4; a++)
#pragma unroll
        for (int b = 0; b < 4; b++)
#pragma unroll
            for (int c = 0; c < 4; c++) acc[a][b][c] = 0.0f;

    const uint4* gA = reinterpret_cast<const uint4*>(g_Fb);
    const uint4* gB = reinterpret_cast<const uint4*>(g_Gb);
    // each thread moves two 16B chunks for A and two for B per K-step
    const int r0 = tid >> 2;            // 0..63
    const int r1 = r0 + 64;             // 64..127
    const int q  = tid & 3;             // 16B chunk within the 64B row slice

    // initial tile (kt = 0)
    {
        uint4 pa0 = gA[(size_t)(rowBase + r0) * (DIM / 8) + q];
        uint4 pa1 = gA[(size_t)(rowBase + r1) * (DIM / 8) + q];
        uint4 pb0 = gB[(size_t)(colBase + r0) * (DIM / 8) + q];
        uint4 pb1 = gB[(size_t)(colBase + r1) * (DIM / 8) + q];
        *reinterpret_cast<uint4*>(&sA[0][r0 * LDA + q * 8]) = pa0;
        *reinterpret_cast<uint4*>(&sA[0][r1 * LDA + q * 8]) = pa1;
        *reinterpret_cast<uint4*>(&sB[0][r0 * LDA + q * 8]) = pb0;
        *reinterpret_cast<uint4*>(&sB[0][r1 * LDA + q * 8]) = pb1;
    }
    __syncthreads();

    const int KT = DIM / BK;  // 32
    // per-lane ldmatrix offsets (in halves, before *2 for bytes)
    const int aRow = wm * 64 + (lane & 15);
    const int aCol = (lane >> 4) << 3;
    const int bRow = wn * 32 + (lane & 7);
    const int bCol = ((lane >> 3) & 1) << 3;

    for (int kt = 0; kt < KT; kt++) {
        const int cur = kt & 1;
        uint4 pa0, pa1, pb0, pb1;
        if (kt + 1 < KT) {
            const int kq = (kt + 1) * 4;  // uint4 offset within row
            pa0 = gA[(size_t)(rowBase + r0) * (DIM / 8) + kq + q];
            pa1 = gA[(size_t)(rowBase + r1) * (DIM / 8) + kq + q];
            pb0 = gB[(size_t)(colBase + r0) * (DIM / 8) + kq + q];
            pb1 = gB[(size_t)(colBase + r1) * (DIM / 8) + kq + q];
        }

        const uint32_t baseA = (uint32_t)__cvta_generic_to_shared(&sA[cur][0]);
        const uint32_t baseB = (uint32_t)__cvta_generic_to_shared(&sB[cur][0]);

#pragma unroll
        for (int kk = 0; kk < 2; kk++) {
            uint32_t af[4][4];
#pragma unroll
            for (int mt = 0; mt < 4; mt++) {
                uint32_t addr = baseA + (uint32_t)(((aRow + mt * 16) * LDA + kk * 16 + aCol) << 1);
                ldmatrix_x4(af[mt][0], af[mt][1], af[mt][2], af[mt][3], addr);
            }
            uint32_t bf[4][2];
#pragma unroll
            for (int nt = 0; nt < 4; nt++) {
                uint32_t addr = baseB + (uint32_t)(((bRow + nt * 8) * LDA + kk * 16 + bCol) << 1);
                ldmatrix_x2(bf[nt][0], bf[nt][1], addr);
            }
#pragma unroll
            for (int mt = 0; mt < 4; mt++)
#pragma unroll
                for (int nt = 0; nt < 4; nt++)
                    mma16816(acc[mt][nt], af[mt][0], af[mt][1], af[mt][2], af[mt][3],
                             bf[nt][0], bf[nt][1]);
        }

        if (kt + 1 < KT) {
            const int nxt = cur ^ 1;
            *reinterpret_cast<uint4*>(&sA[nxt][r0 * LDA + q * 8]) = pa0;
            *reinterpret_cast<uint4*>(&sA[nxt][r1 * LDA + q * 8]) = pa1;
            *reinterpret_cast<uint4*>(&sB[nxt][r0 * LDA + q * 8]) = pb0;
            *reinterpret_cast<uint4*>(&sB[nxt][r1 * LDA + q * 8]) = pb1;
            __syncthreads();
        }
    }

    // ---------- epilogue ----------
    const int g = lane >> 2;   // row group
    const int t = lane & 3;    // col pair

    float wv[4][2];
    int   cl[4][2];
    int   kc[4][2];
#pragma unroll
    for (int nt = 0; nt < 4; nt++)
#pragma unroll
        for (int j = 0; j < 2; j++) {
            int k = colBase + wn * 32 + nt * 8 + t * 2 + j;
            kc[nt][j] = k;
            wv[nt][j] = g_w[k];
            cl[nt][j] = g_cls[k];
        }

#pragma unroll
    for (int mt = 0; mt < 4; mt++) {
#pragma unroll
        for (int h = 0; h < 2; h++) {
            const int i  = rowBase + wm * 64 + mt * 16 + g + h * 8;
            const int ti = g_cls[i];  // i < BATCH always, cls[i] == targets[i]
            float ds = 0.0f, ps = 0.0f;
#pragma unroll
            for (int nt = 0; nt < 4; nt++)
#pragma unroll
                for (int j = 0; j < 2; j++) {
                    float e = __expf(acc[mt][nt][h * 2 + j] * TAU_INV);
                    ds += e * wv[nt][j];
                    if (cl[nt][j] == ti && kc[nt][j] != i)
                        ps += __logf(e + EPSF);
                }
            ds += __shfl_xor_sync(0xffffffffu, ds, 1);
            ds += __shfl_xor_sync(0xffffffffu, ds, 2);
            ps += __shfl_xor_sync(0xffffffffu, ps, 1);
            ps += __shfl_xor_sync(0xffffffffu, ps, 2);
            if (t == 0) {
                int lr = wm * 64 + mt * 16 + g + h * 8;
                atomicAdd(&red_d[lr], ds);
                atomicAdd(&red_p[lr], ps);
            }
        }
    }
    __syncthreads();
    if (tid < BM) {
        g_dpart[bn * BATCH + rowBase + tid] = red_d[tid];
        g_ppart[bn * BATCH + rowBase + tid] = red_p[tid];
    }
}

// ---------------- finalize (deterministic single-block reduction) ----------------
__global__ void k_final(const int* __restrict__ targets, float* __restrict__ out) {
    __shared__ float sred[1024];
    const int tid = threadIdx.x;
    float local = 0.0f;
    for (int r = tid; r < BATCH; r += 1024) {
        float d = 0.0f, p = 0.0f;
#pragma unroll
        for (int b = 0; b < NBLK; b++) {
            d += g_dpart[b * BATCH + r];
            p += g_ppart[b * BATCH + r];
        }
        const float np = (float)g_counts[targets[r]];
        local += logf(d + EPSF) - p / np;
    }
    sred[tid] = local;
    __syncthreads();
    for (int s = 512; s > 0; s >>= 1) {
        if (tid < s) sred[tid] += sred[tid + s];
        __syncthreads();
    }
    if (tid == 0) out[0] = sred[0] / (float)BATCH;
}

// ---------------- launch ----------------
extern "C" void kernel_launch(void* const* d_in, const int* in_sizes, int n_in,
                              void* d_out, int out_size) {
    const float* centers  = nullptr;
    const float* features = nullptr;
    const int*   targets  = nullptr;
    for (int i = 0; i < n_in; i++) {
        if (in_sizes[i] == BATCH)            targets  = (const int*)d_in[i];
        else if (in_sizes[i] == BATCH * DIM) features = (const float*)d_in[i];
        else if (in_sizes[i] == NC * DIM)    centers  = (const float*)d_in[i];
    }

    k_zero_counts<<<1, 1024>>>();
    k_count<<<(BATCH + 255) / 256, 256>>>(targets);
    k_wcls<<<(NPAD + 255) / 256, 256>>>(targets);
    k_convert<<<(NPAD * DIM + 255) / 256, 256>>>(features, centers);

    dim3 grid(NPAD / BN, BATCH / BM);  // (40, 32)
    k_gemm<<<grid, 256>>>();

    k_final<<<1, 1024>>>(targets, (float*)d_out);
}

// round 3
// speedup vs baseline: 1.3880x; 1.3880x over previous
#include <cuda_runtime.h>
#include <cuda_bf16.h>
#include <cstdint>

#define BATCH 4096
#define DIM   1024
#define NC    1000
#define NTOT  5096
#define NPAD  5120
#define TAU_INV 10.0f
#define EPSF 1e-8f

#define BM 128
#define BN 128
#define BK 32
#define LDA 40              // BK + 8 halves pad
#define NBLK (NPAD / BN)    // 40 column blocks
#define NFB  (BATCH / BM)   // 32 feature row/col blocks

// ---- scratch (no allocations allowed) ----
__device__ __nv_bfloat16 g_Gb[NPAD * DIM];         // [features; centers; zero-pad] bf16
__device__ float g_w[NPAD];
__device__ int   g_cls[NPAD];
__device__ int   g_counts[NC];
__device__ float g_dpart[NBLK * BATCH];            // [slot][row] partial denom
__device__ float g_ppart[NBLK * BATCH];            // [slot][row] partial pos-log-sum

// ---------------- prep kernels ----------------
__global__ void k_zero_counts() {
    if (threadIdx.x < NC) g_counts[threadIdx.x] = 0;
}

__global__ void k_count(const int* __restrict__ targets) {
    int i = blockIdx.x * blockDim.x + threadIdx.x;
    if (i < BATCH) atomicAdd(&g_counts[targets[i]], 1);
}

__global__ void k_wcls(const int* __restrict__ targets) {
    int k = blockIdx.x * blockDim.x + threadIdx.x;
    if (k >= NPAD) return;
    if (k < BATCH) {
        int t = targets[k];
        g_w[k]   = 1.0f / (float)(g_counts[t] + 1);
        g_cls[k] = t;
    } else if (k < NTOT) {
        int j = k - BATCH;
        g_w[k]   = 1.0f / (float)(g_counts[j] + 1);
        g_cls[k] = j;
    } else {
        g_w[k]   = 0.0f;
        g_cls[k] = -1;
    }
}

// fp32 -> bf16 convert, 8 elems (16B out) per thread
__global__ void k_convert(const float* __restrict__ features,
                          const float* __restrict__ centers) {
    int idx = blockIdx.x * blockDim.x + threadIdx.x;   // 0 .. NPAD*DIM/8-1
    if (idx >= NPAD * DIM / 8) return;
    int row  = idx >> 7;
    int col0 = (idx & 127) << 3;

    float4 v0, v1;
    if (row < BATCH) {
        const float4* p = reinterpret_cast<const float4*>(features + (size_t)row * DIM + col0);
        v0 = p[0]; v1 = p[1];
    } else if (row < NTOT) {
        const float4* p = reinterpret_cast<const float4*>(centers + (size_t)(row - BATCH) * DIM + col0);
        v0 = p[0]; v1 = p[1];
    } else {
        v0 = make_float4(0.f, 0.f, 0.f, 0.f); v1 = v0;
    }
    __nv_bfloat162 b0 = __nv_bfloat162(__float2bfloat16_rn(v0.x), __float2bfloat16_rn(v0.y));
    __nv_bfloat162 b1 = __nv_bfloat162(__float2bfloat16_rn(v0.z), __float2bfloat16_rn(v0.w));
    __nv_bfloat162 b2 = __nv_bfloat162(__float2bfloat16_rn(v1.x), __float2bfloat16_rn(v1.y));
    __nv_bfloat162 b3 = __nv_bfloat162(__float2bfloat16_rn(v1.z), __float2bfloat16_rn(v1.w));
    uint4 pk;
    pk.x = *reinterpret_cast<uint32_t*>(&b0);
    pk.y = *reinterpret_cast<uint32_t*>(&b1);
    pk.z = *reinterpret_cast<uint32_t*>(&b2);
    pk.w = *reinterpret_cast<uint32_t*>(&b3);
    *reinterpret_cast<uint4*>(g_Gb + (size_t)row * DIM + col0) = pk;
}

// ---------------- mma helpers ----------------
__device__ __forceinline__ void ldmatrix_x4(uint32_t& r0, uint32_t& r1, uint32_t& r2, uint32_t& r3,
                                            uint32_t addr) {
    asm volatile("ldmatrix.sync.aligned.m8n8.x4.shared.b16 {%0,%1,%2,%3}, [%4];"
                 : "=r"(r0), "=r"(r1), "=r"(r2), "=r"(r3) : "r"(addr));
}
__device__ __forceinline__ void ldmatrix_x2(uint32_t& r0, uint32_t& r1, uint32_t addr) {
    asm volatile("ldmatrix.sync.aligned.m8n8.x2.shared.b16 {%0,%1}, [%2];"
                 : "=r"(r0), "=r"(r1) : "r"(addr));
}
__device__ __forceinline__ void mma16816(float* c, uint32_t a0, uint32_t a1, uint32_t a2, uint32_t a3,
                                         uint32_t b0, uint32_t b1) {
    asm volatile(
        "mma.sync.aligned.m16n8k16.row.col.f32.bf16.bf16.f32 "
        "{%0,%1,%2,%3}, {%4,%5,%6,%7}, {%8,%9}, {%0,%1,%2,%3};"
        : "+f"(c[0]), "+f"(c[1]), "+f"(c[2]), "+f"(c[3])
        : "r"(a0), "r"(a1), "r"(a2), "r"(a3), "r"(b0), "r"(b1));
}

// ---------------- fused GEMM + dual-role epilogue ----------------
// Computes tiles with bn >= bm only. For F-F strict-upper tiles (bm < bn < 32)
// the accumulators also serve the transposed tile via column reductions.
__global__ __launch_bounds__(256) void k_gemm() {
    const int bn = blockIdx.x, bm = blockIdx.y;
    if (bn < bm) return;  // lower triangle of F-F region: served by transpose

    __shared__ __align__(16) __nv_bfloat16 sA[2][BM * LDA];
    __shared__ __align__(16) __nv_bfloat16 sB[2][BN * LDA];
    __shared__ float red_d[BM];
    __shared__ float red_p[BM];
    __shared__ float cred_d[BN];
    __shared__ float cred_p[BN];
    __shared__ float sWr[BM];

    const int tid  = threadIdx.x;
    const int warp = tid >> 5;
    const int lane = tid & 31;
    const int wm = warp >> 2;       // 0..1
    const int wn = warp & 3;        // 0..3
    const int rowBase = bm * BM;
    const int colBase = bn * BN;
    const bool doTrans = (bn > bm) && (bn < NFB);

    if (tid < BM) {
        red_d[tid] = 0.0f; red_p[tid] = 0.0f;
        cred_d[tid] = 0.0f; cred_p[tid] = 0.0f;
        sWr[tid] = g_w[rowBase + tid];
    }

    float acc[4][4][4];
#pragma unroll
    for (int a = 0; a < 4; a++)
#pragma unroll
        for (int b = 0; b < 4; b++)
#pragma unroll
            for (int c = 0; c < 4; c++) acc[a][b][c] = 0.0f;

    const uint4* gG = reinterpret_cast<const uint4*>(g_Gb);
    const int r0 = tid >> 2;
    const int r1 = r0 + 64;
    const int q  = tid & 3;

    {
        uint4 pa0 = gG[(size_t)(rowBase + r0) * (DIM / 8) + q];
        uint4 pa1 = gG[(size_t)(rowBase + r1) * (DIM / 8) + q];
        uint4 pb0 = gG[(size_t)(colBase + r0) * (DIM / 8) + q];
        uint4 pb1 = gG[(size_t)(colBase + r1) * (DIM / 8) + q];
        *reinterpret_cast<uint4*>(&sA[0][r0 * LDA + q * 8]) = pa0;
        *reinterpret_cast<uint4*>(&sA[0][r1 * LDA + q * 8]) = pa1;
        *reinterpret_cast<uint4*>(&sB[0][r0 * LDA + q * 8]) = pb0;
        *reinterpret_cast<uint4*>(&sB[0][r1 * LDA + q * 8]) = pb1;
    }
    __syncthreads();

    const int KT = DIM / BK;  // 32
    const int aRow = wm * 64 + (lane & 15);
    const int aCol = (lane >> 4) << 3;
    const int bRow = wn * 32 + (lane & 7);
    const int bCol = ((lane >> 3) & 1) << 3;

    for (int kt = 0; kt < KT; kt++) {
        const int cur = kt & 1;
        uint4 pa0, pa1, pb0, pb1;
        if (kt + 1 < KT) {
            const int kq = (kt + 1) * 4;
            pa0 = gG[(size_t)(rowBase + r0) * (DIM / 8) + kq + q];
            pa1 = gG[(size_t)(rowBase + r1) * (DIM / 8) + kq + q];
            pb0 = gG[(size_t)(colBase + r0) * (DIM / 8) + kq + q];
            pb1 = gG[(size_t)(colBase + r1) * (DIM / 8) + kq + q];
        }

        const uint32_t baseA = (uint32_t)__cvta_generic_to_shared(&sA[cur][0]);
        const uint32_t baseB = (uint32_t)__cvta_generic_to_shared(&sB[cur][0]);

#pragma unroll
        for (int kk = 0; kk < 2; kk++) {
            uint32_t af[4][4];
#pragma unroll
            for (int mt = 0; mt < 4; mt++) {
                uint32_t addr = baseA + (uint32_t)(((aRow + mt * 16) * LDA + kk * 16 + aCol) << 1);
                ldmatrix_x4(af[mt][0], af[mt][1], af[mt][2], af[mt][3], addr);
            }
            uint32_t bf[4][2];
#pragma unroll
            for (int nt = 0; nt < 4; nt++) {
                uint32_t addr = baseB + (uint32_t)(((bRow + nt * 8) * LDA + kk * 16 + bCol) << 1);
                ldmatrix_x2(bf[nt][0], bf[nt][1], addr);
            }
#pragma unroll
            for (int mt = 0; mt < 4; mt++)
#pragma unroll
                for (int nt = 0; nt < 4; nt++)
                    mma16816(acc[mt][nt], af[mt][0], af[mt][1], af[mt][2], af[mt][3],
                             bf[nt][0], bf[nt][1]);
        }

        if (kt + 1 < KT) {
            const int nxt = cur ^ 1;
            *reinterpret_cast<uint4*>(&sA[nxt][r0 * LDA + q * 8]) = pa0;
            *reinterpret_cast<uint4*>(&sA[nxt][r1 * LDA + q * 8]) = pa1;
            *reinterpret_cast<uint4*>(&sB[nxt][r0 * LDA + q * 8]) = pb0;
            *reinterpret_cast<uint4*>(&sB[nxt][r1 * LDA + q * 8]) = pb1;
            __syncthreads();
        }
    }

    // ---------- epilogue ----------
    const int g = lane >> 2;
    const int t = lane & 3;

    float wv[4][2];
    int   cl[4][2];
    int   kc[4][2];
#pragma unroll
    for (int nt = 0; nt < 4; nt++)
#pragma unroll
        for (int j = 0; j < 2; j++) {
            int k = colBase + wn * 32 + nt * 8 + t * 2 + j;
            kc[nt][j] = k;
            wv[nt][j] = g_w[k];
            cl[nt][j] = g_cls[k];
        }

    float cds[4][2], cps[4][2];
#pragma unroll
    for (int nt = 0; nt < 4; nt++)
#pragma unroll
        for (int j = 0; j < 2; j++) { cds[nt][j] = 0.0f; cps[nt][j] = 0.0f; }

#pragma unroll
    for (int mt = 0; mt < 4; mt++) {
#pragma unroll
        for (int h = 0; h < 2; h++) {
            const int lr = wm * 64 + mt * 16 + g + h * 8;
            const int i  = rowBase + lr;
            const int ti = g_cls[i];
            const float wr = sWr[lr];
            float ds = 0.0f, ps = 0.0f;
#pragma unroll
            for (int nt = 0; nt < 4; nt++)
#pragma unroll
                for (int j = 0; j < 2; j++) {
                    const float e = __expf(acc[mt][nt][h * 2 + j] * TAU_INV);
                    ds += e * wv[nt][j];
                    float lg = 0.0f;
                    if (cl[nt][j] == ti && kc[nt][j] != i) lg = __logf(e + EPSF);
                    ps += lg;
                    if (doTrans) {
                        cds[nt][j] += e * wr;   // column k gets exp(s_ik)*w_i
                        cps[nt][j] += lg;       // predicate symmetric in F-F region
                    }
                }
            ds += __shfl_xor_sync(0xffffffffu, ds, 1);
            ds += __shfl_xor_sync(0xffffffffu, ds, 2);
            ps += __shfl_xor_sync(0xffffffffu, ps, 1);
            ps += __shfl_xor_sync(0xffffffffu, ps, 2);
            if (t == 0) {
                atomicAdd(&red_d[lr], ds);
                atomicAdd(&red_p[lr], ps);
            }
        }
    }

    if (doTrans) {
#pragma unroll
        for (int nt = 0; nt < 4; nt++)
#pragma unroll
            for (int j = 0; j < 2; j++) {
                float v = cds[nt][j], p = cps[nt][j];
                v += __shfl_xor_sync(0xffffffffu, v, 4);
                v += __shfl_xor_sync(0xffffffffu, v, 8);
                v += __shfl_xor_sync(0xffffffffu, v, 16);
                p += __shfl_xor_sync(0xffffffffu, p, 4);
                p += __shfl_xor_sync(0xffffffffu, p, 8);
                p += __shfl_xor_sync(0xffffffffu, p, 16);
                if (g == 0) {
                    const int ck = wn * 32 + nt * 8 + t * 2 + j;
                    atomicAdd(&cred_d[ck], v);
                    atomicAdd(&cred_p[ck], p);
                }
            }
    }
    __syncthreads();

    if (tid < BM) {
        g_dpart[bn * BATCH + rowBase + tid] = red_d[tid];
        g_ppart[bn * BATCH + rowBase + tid] = red_p[tid];
        if (doTrans) {
            g_dpart[bm * BATCH + colBase + tid] = cred_d[tid];
            g_ppart[bm * BATCH + colBase + tid] = cred_p[tid];
        }
    }
}

// ---------------- finalize ----------------
__global__ void k_final(const int* __restrict__ targets, float* __restrict__ out) {
    __shared__ float sred[1024];
    const int tid = threadIdx.x;
    float local = 0.0f;
    for (int r = tid; r < BATCH; r += 1024) {
        float d = 0.0f, p = 0.0f;
#pragma unroll
        for (int b = 0; b < NBLK; b++) {
            d += g_dpart[b * BATCH + r];
            p += g_ppart[b * BATCH + r];
        }
        const float np = (float)g_counts[targets[r]];
        local += logf(d + EPSF) - p / np;
    }
    sred[tid] = local;
    __syncthreads();
    for (int s = 512; s > 0; s >>= 1) {
        if (tid < s) sred[tid] += sred[tid + s];
        __syncthreads();
    }
    if (tid == 0) out[0] = sred[0] / (float)BATCH;
}

// ---------------- launch ----------------
extern "C" void kernel_launch(void* const* d_in, const int* in_sizes, int n_in,
                              void* d_out, int out_size) {
    const float* centers  = nullptr;
    const float* features = nullptr;
    const int*   targets  = nullptr;
    for (int i = 0; i < n_in; i++) {
        if (in_sizes[i] == BATCH)            targets  = (const int*)d_in[i];
        else if (in_sizes[i] == BATCH * DIM) features = (const float*)d_in[i];
        else if (in_sizes[i] == NC * DIM)    centers  = (const float*)d_in[i];
    }

    k_zero_counts<<<1, 1024>>>();
    k_count<<<(BATCH + 255) / 256, 256>>>(targets);
    k_wcls<<<(NPAD + 255) / 256, 256>>>(targets);
    k_convert<<<(NPAD * DIM / 8 + 255) / 256, 256>>>(features, centers);

    dim3 grid(NBLK, NFB);  // (40, 32); lower-triangle F-F blocks early-exit
    k_gemm<<<grid, 256>>>();

    k_final<<<1, 1024>>>(targets, (float*)d_out);
}